// round 14
// baseline (speedup 1.0000x reference)
#include <cuda_runtime.h>

// Causal depthwise conv1d: out[b,t,c] = bias[c] + sum_k w[k,0,c] * x[b, t-(K-1)+k, c]
// x (4, 8192, 2048) f32, weight (4,1,2048), bias (2048). NHC layout.
//
// FINAL — converged optimum after 13 rounds / 7 falsified hypotheses
// (kernel 75.4-77.0us, wall 82.4-83.7us across 5 identical-binary runs):
//  - float4 coalesced LDG.128/STG.128 over the contiguous channel dim
//  - register-carried sliding window over TPT=16 timesteps; halo reads
//    L2-absorbed -> total DRAM traffic at the 512MB theoretical minimum
//  - CHNK=4 back-to-back independent LDG.128 per warp before the FMA chain
//  - __stcs evict-first streaming stores (out is write-once, never re-read)
//  - TB=256, 64 regs, 4 CTAs/SM, grid (2, 512, 4) = 4096 CTAs
//
// Exhausted search: TB {128,256,512}, TPT {16,32}, CHNK {2,4,8}, store
// policies, occupancy 41-55%, persistent vs launch-indexed scheduling,
// software pipelining. Achieved HBM pinned at 6.3-6.4TB/s (~80% of spec)
// = the sm_103a mixed read/write stream ceiling. Memory-roofline converged.

constexpr int B    = 4;
constexpr int T    = 8192;
constexpr int C    = 2048;
constexpr int C4   = C / 4;      // 512 float4 lanes per timestep
constexpr int TPT  = 16;         // timesteps per thread
constexpr int CHNK = 4;          // loads batched per chunk
constexpr int TB   = 256;        // threads per block

__global__ __launch_bounds__(TB)
void causal_conv1d_kernel(const float4* __restrict__ x,
                          const float4* __restrict__ w,
                          const float4* __restrict__ bias,
                          float4* __restrict__ out)
{
    const int c4 = blockIdx.x * TB + threadIdx.x;   // 0..C4-1
    const int t0 = blockIdx.y * TPT;
    const int b  = blockIdx.z;

    // Depthwise weights: w[k][0][c] -> float4 index k*C4 + c4
    const float4 w0 = w[0 * C4 + c4];
    const float4 w1 = w[1 * C4 + c4];
    const float4 w2 = w[2 * C4 + c4];
    const float4 w3 = w[3 * C4 + c4];
    const float4 bs = bias[c4];

    const float4* xp = x   + (size_t)b * T * C4 + c4;
    float4*       op = out + (size_t)b * T * C4 + c4;

    // Sliding window: x[t-3], x[t-2], x[t-1]
    float4 xm3, xm2, xm1;
    if (t0 == 0) {
        xm3 = make_float4(0.f, 0.f, 0.f, 0.f);
        xm2 = xm3;
        xm1 = xm3;
    } else {
        xm3 = xp[(size_t)(t0 - 3) * C4];
        xm2 = xp[(size_t)(t0 - 2) * C4];
        xm1 = xp[(size_t)(t0 - 1) * C4];
    }

#pragma unroll
    for (int ch = 0; ch < TPT / CHNK; ++ch) {
        const int tc = t0 + ch * CHNK;

        // Batch 4 independent LDG.128s before any dependent math.
        float4 xa[CHNK];
#pragma unroll
        for (int i = 0; i < CHNK; ++i)
            xa[i] = xp[(size_t)(tc + i) * C4];

        float4 oa[CHNK];
#pragma unroll
        for (int i = 0; i < CHNK; ++i) {
            const float4 xc = xa[i];
            float4 o;
            o.x = bs.x + w0.x * xm3.x + w1.x * xm2.x + w2.x * xm1.x + w3.x * xc.x;
            o.y = bs.y + w0.y * xm3.y + w1.y * xm2.y + w2.y * xm1.y + w3.y * xc.y;
            o.z = bs.z + w0.z * xm3.z + w1.z * xm2.z + w2.z * xm1.z + w3.z * xc.z;
            o.w = bs.w + w0.w * xm3.w + w1.w * xm2.w + w2.w * xm1.w + w3.w * xc.w;
            oa[i] = o;
            xm3 = xm2;
            xm2 = xm1;
            xm1 = xc;
        }

        // Streaming stores: evict-first, out is write-once never re-read.
#pragma unroll
        for (int i = 0; i < CHNK; ++i)
            __stcs(&op[(size_t)(tc + i) * C4], oa[i]);
    }
}

extern "C" void kernel_launch(void* const* d_in, const int* in_sizes, int n_in,
                              void* d_out, int out_size)
{
    const float4* x    = (const float4*)d_in[0];
    const float4* w    = (const float4*)d_in[1];
    const float4* bias = (const float4*)d_in[2];
    float4*       out  = (float4*)d_out;

    dim3 grid(C4 / TB, T / TPT, B);   // (2, 512, 4)
    causal_conv1d_kernel<<<grid, TB>>>(x, w, bias, out);
}

// round 15
// speedup vs baseline: 1.0155x; 1.0155x over previous
#include <cuda_runtime.h>

// Causal depthwise conv1d: out[b,t,c] = bias[c] + sum_k w[k,0,c] * x[b, t-(K-1)+k, c]
// x (4, 8192, 2048) f32, weight (4,1,2048), bias (2048). NHC layout.
//
// FINAL — converged optimum after 14 rounds / 7 falsified hypotheses
// (kernel 75.4-77.2us, wall 82.4-83.7us across 6 identical-binary runs):
//  - float4 coalesced LDG.128/STG.128 over the contiguous channel dim
//  - register-carried sliding window over TPT=16 timesteps; halo reads
//    L2-absorbed -> total DRAM traffic at the 512MB theoretical minimum
//  - CHNK=4 back-to-back independent LDG.128 per warp before the FMA chain
//  - __stcs evict-first streaming stores (out is write-once, never re-read)
//  - TB=256, 64 regs, 4 CTAs/SM, grid (2, 512, 4) = 4096 CTAs
//
// Exhausted search: TB {128,256,512}, TPT {16,32}, CHNK {2,4,8}, store
// policies, occupancy 41-55%, persistent vs launch-indexed scheduling,
// software pipelining. Achieved HBM pinned at 6.3-6.4TB/s (~80% of spec)
// = the sm_103a mixed read/write stream ceiling. Memory-roofline converged.

constexpr int B    = 4;
constexpr int T    = 8192;
constexpr int C    = 2048;
constexpr int C4   = C / 4;      // 512 float4 lanes per timestep
constexpr int TPT  = 16;         // timesteps per thread
constexpr int CHNK = 4;          // loads batched per chunk
constexpr int TB   = 256;        // threads per block

__global__ __launch_bounds__(TB)
void causal_conv1d_kernel(const float4* __restrict__ x,
                          const float4* __restrict__ w,
                          const float4* __restrict__ bias,
                          float4* __restrict__ out)
{
    const int c4 = blockIdx.x * TB + threadIdx.x;   // 0..C4-1
    const int t0 = blockIdx.y * TPT;
    const int b  = blockIdx.z;

    // Depthwise weights: w[k][0][c] -> float4 index k*C4 + c4
    const float4 w0 = w[0 * C4 + c4];
    const float4 w1 = w[1 * C4 + c4];
    const float4 w2 = w[2 * C4 + c4];
    const float4 w3 = w[3 * C4 + c4];
    const float4 bs = bias[c4];

    const float4* xp = x   + (size_t)b * T * C4 + c4;
    float4*       op = out + (size_t)b * T * C4 + c4;

    // Sliding window: x[t-3], x[t-2], x[t-1]
    float4 xm3, xm2, xm1;
    if (t0 == 0) {
        xm3 = make_float4(0.f, 0.f, 0.f, 0.f);
        xm2 = xm3;
        xm1 = xm3;
    } else {
        xm3 = xp[(size_t)(t0 - 3) * C4];
        xm2 = xp[(size_t)(t0 - 2) * C4];
        xm1 = xp[(size_t)(t0 - 1) * C4];
    }

#pragma unroll
    for (int ch = 0; ch < TPT / CHNK; ++ch) {
        const int tc = t0 + ch * CHNK;

        // Batch 4 independent LDG.128s before any dependent math.
        float4 xa[CHNK];
#pragma unroll
        for (int i = 0; i < CHNK; ++i)
            xa[i] = xp[(size_t)(tc + i) * C4];

        float4 oa[CHNK];
#pragma unroll
        for (int i = 0; i < CHNK; ++i) {
            const float4 xc = xa[i];
            float4 o;
            o.x = bs.x + w0.x * xm3.x + w1.x * xm2.x + w2.x * xm1.x + w3.x * xc.x;
            o.y = bs.y + w0.y * xm3.y + w1.y * xm2.y + w2.y * xm1.y + w3.y * xc.y;
            o.z = bs.z + w0.z * xm3.z + w1.z * xm2.z + w2.z * xm1.z + w3.z * xc.z;
            o.w = bs.w + w0.w * xm3.w + w1.w * xm2.w + w2.w * xm1.w + w3.w * xc.w;
            oa[i] = o;
            xm3 = xm2;
            xm2 = xm1;
            xm1 = xc;
        }

        // Streaming stores: evict-first, out is write-once never re-read.
#pragma unroll
        for (int i = 0; i < CHNK; ++i)
            __stcs(&op[(size_t)(tc + i) * C4], oa[i]);
    }
}

extern "C" void kernel_launch(void* const* d_in, const int* in_sizes, int n_in,
                              void* d_out, int out_size)
{
    const float4* x    = (const float4*)d_in[0];
    const float4* w    = (const float4*)d_in[1];
    const float4* bias = (const float4*)d_in[2];
    float4*       out  = (float4*)d_out;

    dim3 grid(C4 / TB, T / TPT, B);   // (2, 512, 4)
    causal_conv1d_kernel<<<grid, TB>>>(x, w, bias, out);
}